// round 10
// baseline (speedup 1.0000x reference)
#include <cuda_runtime.h>
#include <cuda_fp16.h>
#include <cstdint>

#define BATCH 32768
#define HD 512
typedef __half fp16;

// ---------------- device scratch (no allocations allowed) ----------------
__device__ fp16 g_x1[BATCH * HD];
__device__ fp16 g_u1[BATCH * HD], g_u2[BATCH * HD];
__device__ fp16 g_t1[BATCH * HD], g_t2[BATCH * HD];
__device__ float g_P[(size_t)BATCH * 4 * HD];     // z_pre | k | v | d_pre
__device__ float g_z[BATCH * HD];
__device__ fp16 g_W_in[HD * HD];
__device__ fp16 g_W_cat[4 * HD * HD];
__device__ fp16 g_W_h[HD * HD];

// ---------------- helpers ----------------
__device__ __forceinline__ uint32_t smem_u32(const void* p) {
    return (uint32_t)__cvta_generic_to_shared(p);
}
__device__ __forceinline__ void cp16(uint32_t dst, const void* src) {
    asm volatile("cp.async.cg.shared.global [%0], [%1], 16;\n" :: "r"(dst), "l"(src));
}
__device__ __forceinline__ void ldm4(uint32_t (&r)[4], uint32_t addr) {
    asm volatile("ldmatrix.sync.aligned.m8n8.x4.shared.b16 {%0,%1,%2,%3}, [%4];\n"
                 : "=r"(r[0]), "=r"(r[1]), "=r"(r[2]), "=r"(r[3]) : "r"(addr));
}
__device__ __forceinline__ void mma16816(float (&d)[4], const uint32_t (&a)[4],
                                         uint32_t b0, uint32_t b1) {
    asm volatile("mma.sync.aligned.m16n8k16.row.col.f32.f16.f16.f32 "
                 "{%0,%1,%2,%3}, {%4,%5,%6,%7}, {%8,%9}, {%0,%1,%2,%3};\n"
                 : "+f"(d[0]), "+f"(d[1]), "+f"(d[2]), "+f"(d[3])
                 : "r"(a[0]), "r"(a[1]), "r"(a[2]), "r"(a[3]), "r"(b0), "r"(b1));
}
__device__ __forceinline__ float sigf(float x) { return 1.0f / (1.0f + __expf(-x)); }

__device__ __forceinline__ void split_store2(fp16* hi, fp16* lo, float a, float b) {
    fp16 ha = __float2half_rn(a);
    fp16 hb = __float2half_rn(b);
    *reinterpret_cast<__half2*>(hi) = __halves2half2(ha, hb);
    fp16 la = __float2half_rn(a - __half2float(ha));
    fp16 lb = __float2half_rn(b - __half2float(hb));
    *reinterpret_cast<__half2*>(lo) = __halves2half2(la, lb);
}

// ---------------- weight prep: transpose to [N][K] fp16 ----------------
__global__ void prep_weights(const float* __restrict__ W_in, const float* __restrict__ W_z,
                             const float* __restrict__ W_k, const float* __restrict__ W_v,
                             const float* __restrict__ W_d, const float* __restrict__ W_h) {
    int idx = blockIdx.x * 256 + threadIdx.x;
    if (idx >= 6 * HD * HD) return;
    int mat = idx / (HD * HD);
    int e = idx % (HD * HD);
    int k = e / HD, n = e % HD;
    const float* W;
    fp16* D;
    int dst;
    if (mat == 0) {
        W = W_in; D = g_W_in; dst = n * HD + k;
    } else if (mat <= 4) {
        W = (mat == 1) ? W_z : (mat == 2) ? W_k : (mat == 3) ? W_v : W_d;
        D = g_W_cat; dst = ((mat - 1) * HD + n) * HD + k;
    } else {
        W = W_h; D = g_W_h; dst = n * HD + k;
    }
    D[dst] = __float2half_rn(W[e]);
}

// ---------------- x -> single fp16 ----------------
__global__ void conv_x_kernel(const float* __restrict__ x) {
    int i = blockIdx.x * 256 + threadIdx.x;  // float4 index
    float4 v = reinterpret_cast<const float4*>(x)[i];
    __half2 a = __halves2half2(__float2half_rn(v.x), __float2half_rn(v.y));
    __half2 b = __halves2half2(__float2half_rn(v.z), __float2half_rn(v.w));
    *reinterpret_cast<__half2*>(g_x1 + (size_t)i * 4) = a;
    *reinterpret_cast<__half2*>(g_x1 + (size_t)i * 4 + 2) = b;
}

// ================= fused full-row GEMM (BM=64, BN=512) =================
#define FBM 64
#define FBK 32
#define KST 40                              // padded fp16 row stride (80 B)
#define F_ATILE (FBM * KST * 2)             // 5120 B
#define F_BTILE (HD * KST * 2)              // 40960 B
#define SCR_STRIDE 520                      // floats; 2080 B, 16B-aligned

// ---- fused GEMM1: u = LN(x @ W_in + b_in); store u as fp16 hi/lo ----
#define SMEM_F1 (2 * (F_ATILE + F_BTILE))   // 92160
__global__ void __launch_bounds__(256, 1) fused_gemm1(
    const float* __restrict__ bias, const float* __restrict__ gamma,
    const float* __restrict__ beta) {
    extern __shared__ __align__(16) char smc[];
    const int tid = threadIdx.x;
    const int warp = tid >> 5, lane = tid & 31;
    const int m0 = blockIdx.x * FBM;
    const int wm = (warp >> 2) * 32;    // 2 M groups
    const int wn = (warp & 3) * 128;    // 4 N groups

    float acc[2][16][4];
#pragma unroll
    for (int a = 0; a < 2; a++)
#pragma unroll
        for (int b = 0; b < 16; b++)
#pragma unroll
            for (int c = 0; c < 4; c++) acc[a][b][c] = 0.f;

    auto tA = [&](int st) -> char* { return smc + (size_t)st * (F_ATILE + F_BTILE); };
    auto tB = [&](int st) -> char* { return tA(st) + F_ATILE; };

    auto load_stage = [&](int s) {
        const int st = s & 1;
        const int k0 = s * FBK;
        {   // A: 64 rows x 4 chunks = 256
            int row = tid >> 2, col = (tid & 3) * 8;
            cp16(smem_u32(tA(st)) + (uint32_t)(row * KST + col) * 2,
                 g_x1 + (size_t)(m0 + row) * HD + k0 + col);
        }
#pragma unroll
        for (int i = 0; i < 8; i++) {       // B: 512 rows x 4 chunks = 2048
            int c = i * 256 + tid;
            int row = c >> 2, col = (c & 3) * 8;
            cp16(smem_u32(tB(st)) + (uint32_t)(row * KST + col) * 2,
                 g_W_in + (size_t)row * HD + k0 + col);
        }
        asm volatile("cp.async.commit_group;\n");
    };

    load_stage(0);
    load_stage(1);

    for (int s = 0; s < 16; ++s) {
        const int st = s & 1;
        if (s == 15) asm volatile("cp.async.wait_group 0;\n");
        else         asm volatile("cp.async.wait_group 1;\n");
        __syncthreads();
        const fp16* At = reinterpret_cast<const fp16*>(tA(st));
        const fp16* Bt = reinterpret_cast<const fp16*>(tB(st));
#pragma unroll
        for (int kk = 0; kk < FBK; kk += 16) {
            uint32_t aF[2][4];
#pragma unroll
            for (int mi = 0; mi < 2; mi++)
                ldm4(aF[mi], smem_u32(At + (wm + mi * 16 + (lane & 15)) * KST
                                         + kk + ((lane >> 4) << 3)));
            uint32_t bF[8][4];
#pragma unroll
            for (int nb = 0; nb < 8; nb++)
                ldm4(bF[nb], smem_u32(Bt + (wn + nb * 16 + (lane & 7) + ((lane >> 4) << 3)) * KST
                                         + kk + (((lane >> 3) & 1) << 3)));
#pragma unroll
            for (int mi = 0; mi < 2; mi++)
#pragma unroll
                for (int ni = 0; ni < 16; ni++)
                    mma16816(acc[mi][ni], aF[mi], bF[ni >> 1][(ni & 1) * 2],
                             bF[ni >> 1][(ni & 1) * 2 + 1]);
        }
        __syncthreads();
        if (s + 2 < 16) load_stage(s + 2);
    }

    // fused epilogue: two 32-row chunks through smem scratch
    float* scr = reinterpret_cast<float*>(smc);
    for (int ch = 0; ch < 2; ch++) {
        __syncthreads();
        if ((warp >> 2) == ch) {
#pragma unroll
            for (int mi = 0; mi < 2; mi++)
#pragma unroll
                for (int ni = 0; ni < 16; ni++) {
                    int r = mi * 16 + (lane >> 2);
                    int c = wn + ni * 8 + (lane & 3) * 2;
                    *reinterpret_cast<float2*>(&scr[r * SCR_STRIDE + c]) =
                        make_float2(acc[mi][ni][0], acc[mi][ni][1]);
                    *reinterpret_cast<float2*>(&scr[(r + 8) * SCR_STRIDE + c]) =
                        make_float2(acc[mi][ni][2], acc[mi][ni][3]);
                }
        }
        __syncthreads();
#pragma unroll
        for (int rr = 0; rr < 4; rr++) {
            int lr = warp * 4 + rr;
            int grow = m0 + ch * 32 + lr;
            const float* p = scr + lr * SCR_STRIDE;
            float v[16];
            float sm = 0.f, sq = 0.f;
#pragma unroll
            for (int i = 0; i < 4; i++) {
                int c = i * 128 + lane * 4;
                float4 x4 = *reinterpret_cast<const float4*>(p + c);
                float4 b4 = *reinterpret_cast<const float4*>(bias + c);
                float t0 = x4.x + b4.x, t1 = x4.y + b4.y, t2 = x4.z + b4.z, t3 = x4.w + b4.w;
                v[i * 4 + 0] = t0; v[i * 4 + 1] = t1; v[i * 4 + 2] = t2; v[i * 4 + 3] = t3;
                sm += t0 + t1 + t2 + t3;
                sq += t0 * t0 + t1 * t1 + t2 * t2 + t3 * t3;
            }
#pragma unroll
            for (int o = 16; o; o >>= 1) {
                sm += __shfl_xor_sync(0xffffffffu, sm, o);
                sq += __shfl_xor_sync(0xffffffffu, sq, o);
            }
            float mean = sm * (1.f / HD);
            float inv = rsqrtf(fmaxf(sq * (1.f / HD) - mean * mean, 0.f) + 1e-5f);
#pragma unroll
            for (int i = 0; i < 4; i++) {
                int c = i * 128 + lane * 4;
                float4 g4 = *reinterpret_cast<const float4*>(gamma + c);
                float4 b4 = *reinterpret_cast<const float4*>(beta + c);
                float u0 = (v[i * 4 + 0] - mean) * inv * g4.x + b4.x;
                float u1 = (v[i * 4 + 1] - mean) * inv * g4.y + b4.y;
                float u2 = (v[i * 4 + 2] - mean) * inv * g4.z + b4.z;
                float u3 = (v[i * 4 + 3] - mean) * inv * g4.w + b4.w;
                size_t idx = (size_t)grow * HD + c;
                split_store2(g_u1 + idx, g_u2 + idx, u0, u1);
                split_store2(g_u1 + idx + 2, g_u2 + idx + 2, u2, u3);
            }
        }
    }
}

// ---- fused GEMM3: h = (1-z)*tanh(LN(t @ W_h + b_h)) + z*h_prev ----
#define SMEM_F3 (2 * (2 * F_ATILE + F_BTILE))   // 102400
__global__ void __launch_bounds__(256, 1) fused_gemm3(
    const float* __restrict__ bias, const float* __restrict__ gamma,
    const float* __restrict__ beta, const float* __restrict__ h_prev,
    float* __restrict__ out_h) {
    extern __shared__ __align__(16) char smc[];
    const int tid = threadIdx.x;
    const int warp = tid >> 5, lane = tid & 31;
    const int m0 = blockIdx.x * FBM;
    const int wm = (warp >> 2) * 32;
    const int wn = (warp & 3) * 128;

    float acc[2][16][4];
#pragma unroll
    for (int a = 0; a < 2; a++)
#pragma unroll
        for (int b = 0; b < 16; b++)
#pragma unroll
            for (int c = 0; c < 4; c++) acc[a][b][c] = 0.f;

    auto tA = [&](int st, int term) -> char* {
        return smc + (size_t)st * (2 * F_ATILE + F_BTILE) + (size_t)term * F_ATILE;
    };
    auto tB = [&](int st) -> char* { return tA(st, 0) + 2 * F_ATILE; };

    auto load_stage = [&](int s) {
        const int st = s & 1;
        const int k0 = s * FBK;
        {
            int row = tid >> 2, col = (tid & 3) * 8;
            size_t off = (size_t)(m0 + row) * HD + k0 + col;
            uint32_t d = (uint32_t)(row * KST + col) * 2;
            cp16(smem_u32(tA(st, 0)) + d, g_t1 + off);
            cp16(smem_u32(tA(st, 1)) + d, g_t2 + off);
        }
#pragma unroll
        for (int i = 0; i < 8; i++) {
            int c = i * 256 + tid;
            int row = c >> 2, col = (c & 3) * 8;
            cp16(smem_u32(tB(st)) + (uint32_t)(row * KST + col) * 2,
                 g_W_h + (size_t)row * HD + k0 + col);
        }
        asm volatile("cp.async.commit_group;\n");
    };

    load_stage(0);
    load_stage(1);

    for (int s = 0; s < 16; ++s) {
        const int st = s & 1;
        if (s == 15) asm volatile("cp.async.wait_group 0;\n");
        else         asm volatile("cp.async.wait_group 1;\n");
        __syncthreads();
        const fp16* Bt = reinterpret_cast<const fp16*>(tB(st));
#pragma unroll
        for (int term = 0; term < 2; term++) {
            const fp16* At = reinterpret_cast<const fp16*>(tA(st, term));
#pragma unroll
            for (int kk = 0; kk < FBK; kk += 16) {
                uint32_t aF[2][4];
#pragma unroll
                for (int mi = 0; mi < 2; mi++)
                    ldm4(aF[mi], smem_u32(At + (wm + mi * 16 + (lane & 15)) * KST
                                             + kk + ((lane >> 4) << 3)));
                uint32_t bF[8][4];
#pragma unroll
                for (int nb = 0; nb < 8; nb++)
                    ldm4(bF[nb], smem_u32(Bt + (wn + nb * 16 + (lane & 7) + ((lane >> 4) << 3)) * KST
                                             + kk + (((lane >> 3) & 1) << 3)));
#pragma unroll
                for (int mi = 0; mi < 2; mi++)
#pragma unroll
                    for (int ni = 0; ni < 16; ni++)
                        mma16816(acc[mi][ni], aF[mi], bF[ni >> 1][(ni & 1) * 2],
                                 bF[ni >> 1][(ni & 1) * 2 + 1]);
            }
        }
        __syncthreads();
        if (s + 2 < 16) load_stage(s + 2);
    }

    float* scr = reinterpret_cast<float*>(smc);
    for (int ch = 0; ch < 2; ch++) {
        __syncthreads();
        if ((warp >> 2) == ch) {
#pragma unroll
            for (int mi = 0; mi < 2; mi++)
#pragma unroll
                for (int ni = 0; ni < 16; ni++) {
                    int r = mi * 16 + (lane >> 2);
                    int c = wn + ni * 8 + (lane & 3) * 2;
                    *reinterpret_cast<float2*>(&scr[r * SCR_STRIDE + c]) =
                        make_float2(acc[mi][ni][0], acc[mi][ni][1]);
                    *reinterpret_cast<float2*>(&scr[(r + 8) * SCR_STRIDE + c]) =
                        make_float2(acc[mi][ni][2], acc[mi][ni][3]);
                }
        }
        __syncthreads();
#pragma unroll
        for (int rr = 0; rr < 4; rr++) {
            int lr = warp * 4 + rr;
            int grow = m0 + ch * 32 + lr;
            const float* p = scr + lr * SCR_STRIDE;
            float v[16];
            float sm = 0.f, sq = 0.f;
#pragma unroll
            for (int i = 0; i < 4; i++) {
                int c = i * 128 + lane * 4;
                float4 x4 = *reinterpret_cast<const float4*>(p + c);
                float4 b4 = *reinterpret_cast<const float4*>(bias + c);
                float t0 = x4.x + b4.x, t1 = x4.y + b4.y, t2 = x4.z + b4.z, t3 = x4.w + b4.w;
                v[i * 4 + 0] = t0; v[i * 4 + 1] = t1; v[i * 4 + 2] = t2; v[i * 4 + 3] = t3;
                sm += t0 + t1 + t2 + t3;
                sq += t0 * t0 + t1 * t1 + t2 * t2 + t3 * t3;
            }
#pragma unroll
            for (int o = 16; o; o >>= 1) {
                sm += __shfl_xor_sync(0xffffffffu, sm, o);
                sq += __shfl_xor_sync(0xffffffffu, sq, o);
            }
            float mean = sm * (1.f / HD);
            float inv = rsqrtf(fmaxf(sq * (1.f / HD) - mean * mean, 0.f) + 1e-5f);
#pragma unroll
            for (int i = 0; i < 4; i++) {
                int c = i * 128 + lane * 4;
                size_t idx = (size_t)grow * HD + c;
                float4 g4 = *reinterpret_cast<const float4*>(gamma + c);
                float4 b4 = *reinterpret_cast<const float4*>(beta + c);
                float c0 = tanhf((v[i * 4 + 0] - mean) * inv * g4.x + b4.x);
                float c1 = tanhf((v[i * 4 + 1] - mean) * inv * g4.y + b4.y);
                float c2 = tanhf((v[i * 4 + 2] - mean) * inv * g4.z + b4.z);
                float c3 = tanhf((v[i * 4 + 3] - mean) * inv * g4.w + b4.w);
                float4 z4 = *reinterpret_cast<const float4*>(&g_z[idx]);
                float4 hp = *reinterpret_cast<const float4*>(h_prev + idx);
                float h0 = (1.f - z4.x) * c0 + z4.x * hp.x;
                float h1 = (1.f - z4.y) * c1 + z4.y * hp.y;
                float h2 = (1.f - z4.z) * c2 + z4.z * hp.z;
                float h3 = (1.f - z4.w) * c3 + z4.w * hp.w;
                *reinterpret_cast<float4*>(out_h + idx) = make_float4(h0, h1, h2, h3);
            }
        }
    }
}

// ================= GEMM2 (N=2048) : unchanged round-6 structure =================
#define BM 128
#define BN 128
#define BK 32
#define TILEB (BM * KST * 2)           // 10240
#define SMEM_G2 (6 * TILEB)            // 60 KB

__global__ void __launch_bounds__(256, 2) gemm2_kernel() {
    const fp16* A1 = g_u1;
    const fp16* A2 = g_u2;
    const fp16* Bp = g_W_cat;
    float* C = g_P;
    const int N = 4 * HD;

    extern __shared__ __align__(16) char sm[];
    auto tile = [&](int stage, int sel) -> fp16* {
        return reinterpret_cast<fp16*>(sm + (size_t)(stage * 3 + sel) * TILEB);
    };

    const int tid = threadIdx.x;
    const int m0 = blockIdx.y * BM;
    const int n0 = blockIdx.x * BN;
    const int warp = tid >> 5, lane = tid & 31;
    const int wm = (warp >> 1) * 32;
    const int wn = (warp & 1) * 64;

    float acc[2][8][4];
#pragma unroll
    for (int i = 0; i < 2; i++)
#pragma unroll
        for (int j = 0; j < 8; j++)
#pragma unroll
            for (int q = 0; q < 4; q++) acc[i][j][q] = 0.f;

    auto load_stage = [&](int s) {
        const int st = s & 1;
        const int k0 = s * BK;
        fp16* a1 = tile(st, 0);
        fp16* a2 = tile(st, 1);
        fp16* bb = tile(st, 2);
#pragma unroll
        for (int i = 0; i < 2; i++) {
            int c = i * 256 + tid;
            int row = c >> 2;
            int col = (c & 3) * 8;
            uint32_t d = (uint32_t)(row * KST + col) * 2;
            size_t offA = (size_t)(m0 + row) * HD + k0 + col;
            cp16(smem_u32(a1) + d, A1 + offA);
            cp16(smem_u32(a2) + d, A2 + offA);
            size_t offB = (size_t)(n0 + row) * HD + k0 + col;
            cp16(smem_u32(bb) + d, Bp + offB);
        }
        asm volatile("cp.async.commit_group;\n");
    };

    auto compute_pass = [&](const fp16* At, const fp16* Bt) {
#pragma unroll
        for (int kk = 0; kk < BK; kk += 16) {
            uint32_t aF[2][4];
#pragma unroll
            for (int mi = 0; mi < 2; mi++)
                ldm4(aF[mi], smem_u32(At + (wm + mi * 16 + (lane & 15)) * KST
                                         + kk + ((lane >> 4) << 3)));
            uint32_t bF[4][4];
#pragma unroll
            for (int nb = 0; nb < 4; nb++)
                ldm4(bF[nb], smem_u32(Bt + (wn + nb * 16 + (lane & 7) + ((lane >> 4) << 3)) * KST
                                         + kk + (((lane >> 3) & 1) << 3)));
#pragma unroll
            for (int mi = 0; mi < 2; mi++)
#pragma unroll
                for (int ni = 0; ni < 8; ni++)
                    mma16816(acc[mi][ni], aF[mi], bF[ni >> 1][(ni & 1) * 2],
                             bF[ni >> 1][(ni & 1) * 2 + 1]);
        }
    };

    load_stage(0);
    load_stage(1);

    for (int s = 0; s < 16; ++s) {
        const int st = s & 1;
        if (s == 15) asm volatile("cp.async.wait_group 0;\n");
        else         asm volatile("cp.async.wait_group 1;\n");
        __syncthreads();
        compute_pass(tile(st, 0), tile(st, 2));
        compute_pass(tile(st, 1), tile(st, 2));
        __syncthreads();
        if (s + 2 < 16) load_stage(s + 2);
    }

#pragma unroll
    for (int mi = 0; mi < 2; mi++)
#pragma unroll
        for (int ni = 0; ni < 8; ni++) {
            int r = m0 + wm + mi * 16 + (lane >> 2);
            int c = n0 + wn + ni * 8 + (lane & 3) * 2;
            *reinterpret_cast<float2*>(&C[(size_t)r * N + c]) =
                make_float2(acc[mi][ni][0], acc[mi][ni][1]);
            *reinterpret_cast<float2*>(&C[(size_t)(r + 8) * N + c]) =
                make_float2(acc[mi][ni][2], acc[mi][ni][3]);
        }
}

// ---------------- epilogue 1: z, s, t (unchanged) ----------------
__global__ void epi1_kernel(const float* __restrict__ s_prev, const float* __restrict__ bz,
                            const float* __restrict__ glz, const float* __restrict__ blz,
                            const float* __restrict__ bk, const float* __restrict__ bv,
                            const float* __restrict__ bd, float* __restrict__ out_s) {
    int row = blockIdx.x * 8 + (threadIdx.x >> 5);
    int lane = threadIdx.x & 31;
    const float* Pr = g_P + (size_t)row * (4 * HD);
    float zp[16];
    float sm = 0.f, sq = 0.f;
#pragma unroll
    for (int i = 0; i < 4; i++) {
        int c = i * 128 + lane * 4;
        float4 z4 = *reinterpret_cast<const float4*>(Pr + c);
        float4 b4 = *reinterpret_cast<const float4*>(bz + c);
        float t0 = z4.x + b4.x, t1 = z4.y + b4.y, t2 = z4.z + b4.z, t3 = z4.w + b4.w;
        zp[i * 4 + 0] = t0; zp[i * 4 + 1] = t1; zp[i * 4 + 2] = t2; zp[i * 4 + 3] = t3;
        sm += t0 + t1 + t2 + t3;
        sq += t0 * t0 + t1 * t1 + t2 * t2 + t3 * t3;
    }
#pragma unroll
    for (int o = 16; o; o >>= 1) {
        sm += __shfl_xor_sync(0xffffffffu, sm, o);
        sq += __shfl_xor_sync(0xffffffffu, sq, o);
    }
    float mean = sm * (1.f / HD);
    float inv = rsqrtf(fmaxf(sq * (1.f / HD) - mean * mean, 0.f) + 1e-5f);
#pragma unroll
    for (int i = 0; i < 4; i++) {
        int c = i * 128 + lane * 4;
        size_t idx = (size_t)row * HD + c;
        float4 g4 = *reinterpret_cast<const float4*>(glz + c);
        float4 bb4 = *reinterpret_cast<const float4*>(blz + c);
        float z0 = sigf((zp[i * 4 + 0] - mean) * inv * g4.x + bb4.x);
        float z1 = sigf((zp[i * 4 + 1] - mean) * inv * g4.y + bb4.y);
        float z2 = sigf((zp[i * 4 + 2] - mean) * inv * g4.z + bb4.z);
        float z3 = sigf((zp[i * 4 + 3] - mean) * inv * g4.w + bb4.w);

        float4 k4 = *reinterpret_cast<const float4*>(Pr + HD + c);
        float4 bk4 = *reinterpret_cast<const float4*>(bk + c);
        float4 v4 = *reinterpret_cast<const float4*>(Pr + 2 * HD + c);
        float4 bv4 = *reinterpret_cast<const float4*>(bv + c);
        float4 d4 = *reinterpret_cast<const float4*>(Pr + 3 * HD + c);
        float4 bd4 = *reinterpret_cast<const float4*>(bd + c);
        float4 sp = *reinterpret_cast<const float4*>(s_prev + idx);

        float kk0 = k4.x + bk4.x, kk1 = k4.y + bk4.y, kk2 = k4.z + bk4.z, kk3 = k4.w + bk4.w;
        float vv0 = v4.x + bv4.x, vv1 = v4.y + bv4.y, vv2 = v4.z + bv4.z, vv3 = v4.w + bv4.w;
        float dc0 = sigf(d4.x + bd4.x), dc1 = sigf(d4.y + bd4.y);
        float dc2 = sigf(d4.z + bd4.z), dc3 = sigf(d4.w + bd4.w);
        float s0 = dc0 * sp.x + kk0 * vv0;
        float s1 = dc1 * sp.y + kk1 * vv1;
        float s2 = dc2 * sp.z + kk2 * vv2;
        float s3 = dc3 * sp.w + kk3 * vv3;
        *reinterpret_cast<float4*>(out_s + idx) = make_float4(s0, s1, s2, s3);

        __half2 uh0 = *reinterpret_cast<const __half2*>(g_u1 + idx);
        __half2 ul0 = *reinterpret_cast<const __half2*>(g_u2 + idx);
        __half2 uh1 = *reinterpret_cast<const __half2*>(g_u1 + idx + 2);
        __half2 ul1 = *reinterpret_cast<const __half2*>(g_u2 + idx + 2);
        float u0 = __half2float(uh0.x) + __half2float(ul0.x);
        float u1 = __half2float(uh0.y) + __half2float(ul0.y);
        float u2 = __half2float(uh1.x) + __half2float(ul1.x);
        float u3 = __half2float(uh1.y) + __half2float(ul1.y);
        split_store2(g_t1 + idx, g_t2 + idx, u0 + s0, u1 + s1);
        split_store2(g_t1 + idx + 2, g_t2 + idx + 2, u2 + s2, u3 + s3);
        *reinterpret_cast<float4*>(&g_z[idx]) = make_float4(z0, z1, z2, z3);
    }
}

// ---------------- launch ----------------
extern "C" void kernel_launch(void* const* d_in, const int* in_sizes, int n_in,
                              void* d_out, int out_size) {
    const float* x       = (const float*)d_in[0];
    const float* h_prev  = (const float*)d_in[1];
    const float* s_prev  = (const float*)d_in[2];
    const float* W_in    = (const float*)d_in[3];
    const float* b_in    = (const float*)d_in[4];
    const float* g_ln_in = (const float*)d_in[5];
    const float* b_ln_in = (const float*)d_in[6];
    const float* g_ln_z  = (const float*)d_in[9];
    const float* b_ln_z  = (const float*)d_in[10];
    const float* g_ln_h  = (const float*)d_in[11];
    const float* b_ln_h  = (const float*)d_in[12];
    const float* W_z     = (const float*)d_in[15];
    const float* b_z     = (const float*)d_in[16];
    const float* W_k     = (const float*)d_in[17];
    const float* b_k     = (const float*)d_in[18];
    const float* W_v     = (const float*)d_in[19];
    const float* b_v     = (const float*)d_in[20];
    const float* W_h     = (const float*)d_in[21];
    const float* b_h     = (const float*)d_in[22];
    const float* W_d     = (const float*)d_in[23];
    const float* b_d     = (const float*)d_in[24];

    float* out_h = (float*)d_out;
    float* out_s = out_h + (size_t)BATCH * HD;

    cudaFuncSetAttribute(fused_gemm1, cudaFuncAttributeMaxDynamicSharedMemorySize, SMEM_F1);
    cudaFuncSetAttribute(fused_gemm3, cudaFuncAttributeMaxDynamicSharedMemorySize, SMEM_F3);
    cudaFuncSetAttribute(gemm2_kernel, cudaFuncAttributeMaxDynamicSharedMemorySize, SMEM_G2);

    prep_weights<<<(6 * HD * HD + 255) / 256, 256>>>(W_in, W_z, W_k, W_v, W_d, W_h);
    conv_x_kernel<<<BATCH * HD / 4 / 256, 256>>>(x);

    fused_gemm1<<<BATCH / FBM, 256, SMEM_F1>>>(b_in, g_ln_in, b_ln_in);

    gemm2_kernel<<<dim3(4 * HD / BN, BATCH / BM), 256, SMEM_G2>>>();
    epi1_kernel<<<BATCH / 8, 256>>>(s_prev, b_z, g_ln_z, b_ln_z, b_k, b_v, b_d, out_s);

    fused_gemm3<<<BATCH / FBM, 256, SMEM_F3>>>(b_h, g_ln_h, b_ln_h, h_prev, out_h);
}

// round 11
// speedup vs baseline: 1.1978x; 1.1978x over previous
#include <cuda_runtime.h>
#include <cuda_fp16.h>
#include <cstdint>

#define BATCH 32768
#define HD 512
typedef __half fp16;

// ---------------- device scratch (no allocations allowed) ----------------
__device__ fp16 g_x1[BATCH * HD];
__device__ fp16 g_u1[BATCH * HD], g_u2[BATCH * HD];
__device__ fp16 g_t1[BATCH * HD], g_t2[BATCH * HD];
__device__ float g_pre[BATCH * HD];               // GEMM1 out, reused for GEMM3 out
__device__ float g_P[(size_t)BATCH * 4 * HD];     // z_pre | k | v | d_pre
__device__ float g_z[BATCH * HD];
__device__ fp16 g_W_in[HD * HD];
__device__ fp16 g_W_cat[4 * HD * HD];
__device__ fp16 g_W_h[HD * HD];

// ---------------- helpers ----------------
__device__ __forceinline__ uint32_t smem_u32(const void* p) {
    return (uint32_t)__cvta_generic_to_shared(p);
}
__device__ __forceinline__ void cp16(uint32_t dst, const void* src) {
    asm volatile("cp.async.cg.shared.global [%0], [%1], 16;\n" :: "r"(dst), "l"(src));
}
__device__ __forceinline__ void ldm4(uint32_t (&r)[4], uint32_t addr) {
    asm volatile("ldmatrix.sync.aligned.m8n8.x4.shared.b16 {%0,%1,%2,%3}, [%4];\n"
                 : "=r"(r[0]), "=r"(r[1]), "=r"(r[2]), "=r"(r[3]) : "r"(addr));
}
__device__ __forceinline__ void mma16816(float (&d)[4], const uint32_t (&a)[4],
                                         uint32_t b0, uint32_t b1) {
    asm volatile("mma.sync.aligned.m16n8k16.row.col.f32.f16.f16.f32 "
                 "{%0,%1,%2,%3}, {%4,%5,%6,%7}, {%8,%9}, {%0,%1,%2,%3};\n"
                 : "+f"(d[0]), "+f"(d[1]), "+f"(d[2]), "+f"(d[3])
                 : "r"(a[0]), "r"(a[1]), "r"(a[2]), "r"(a[3]), "r"(b0), "r"(b1));
}
__device__ __forceinline__ float sigf(float x) { return 1.0f / (1.0f + __expf(-x)); }

__device__ __forceinline__ void split_store2(fp16* hi, fp16* lo, float a, float b) {
    fp16 ha = __float2half_rn(a);
    fp16 hb = __float2half_rn(b);
    *reinterpret_cast<__half2*>(hi) = __halves2half2(ha, hb);
    fp16 la = __float2half_rn(a - __half2float(ha));
    fp16 lb = __float2half_rn(b - __half2float(hb));
    *reinterpret_cast<__half2*>(lo) = __halves2half2(la, lb);
}

// ---------------- weight prep: transpose to [N][K] fp16 ----------------
__global__ void prep_weights(const float* __restrict__ W_in, const float* __restrict__ W_z,
                             const float* __restrict__ W_k, const float* __restrict__ W_v,
                             const float* __restrict__ W_d, const float* __restrict__ W_h) {
    int idx = blockIdx.x * 256 + threadIdx.x;
    if (idx >= 6 * HD * HD) return;
    int mat = idx / (HD * HD);
    int e = idx % (HD * HD);
    int k = e / HD, n = e % HD;
    const float* W;
    fp16* D;
    int dst;
    if (mat == 0) {
        W = W_in; D = g_W_in; dst = n * HD + k;
    } else if (mat <= 4) {
        W = (mat == 1) ? W_z : (mat == 2) ? W_k : (mat == 3) ? W_v : W_d;
        D = g_W_cat; dst = ((mat - 1) * HD + n) * HD + k;
    } else {
        W = W_h; D = g_W_h; dst = n * HD + k;
    }
    D[dst] = __float2half_rn(W[e]);
}

// ---------------- x -> single fp16 ----------------
__global__ void conv_x_kernel(const float* __restrict__ x) {
    int i = blockIdx.x * 256 + threadIdx.x;  // float4 index
    float4 v = reinterpret_cast<const float4*>(x)[i];
    __half2 a = __halves2half2(__float2half_rn(v.x), __float2half_rn(v.y));
    __half2 b = __halves2half2(__float2half_rn(v.z), __float2half_rn(v.w));
    *reinterpret_cast<__half2*>(g_x1 + (size_t)i * 4) = a;
    *reinterpret_cast<__half2*>(g_x1 + (size_t)i * 4 + 2) = b;
}

// ---------------- GEMM: C[M,N] = A[M,512] @ W[512,N] ----------------
// WHICH==0: A = x (1 term). WHICH==1: A = u1+u2 (2 terms), N=2048.
// WHICH==2: A = t1+t2 (2 terms).
// 3-stage cp.async ring, single __syncthreads per stage, B fragments shared
// across terms.
#define BM 128
#define BN 128
#define BK 32
#define KST 40                         // padded fp16 row stride (80 B)
#define TILEB (BM * KST * 2)           // 10240 bytes

template <int WHICH>
__global__ void __launch_bounds__(256, 2) gemm_kernel() {
    constexpr int NT = (WHICH == 0) ? 1 : 2;
    constexpr int STGB = (NT + 1) * TILEB;
    const fp16* A1 = (WHICH == 0) ? g_x1 : (WHICH == 1) ? g_u1 : g_t1;
    const fp16* A2 = (WHICH == 0) ? g_x1 : (WHICH == 1) ? g_u2 : g_t2;  // unused for 0
    const fp16* Bp = (WHICH == 0) ? g_W_in : (WHICH == 1) ? g_W_cat : g_W_h;
    float* C = (WHICH == 1) ? g_P : g_pre;
    const int N = (WHICH == 1) ? 4 * HD : HD;

    extern __shared__ __align__(16) char smc[];
    auto tA = [&](int st, int t) -> fp16* {
        return reinterpret_cast<fp16*>(smc + (size_t)st * STGB + (size_t)t * TILEB);
    };
    auto tB = [&](int st) -> fp16* {
        return reinterpret_cast<fp16*>(smc + (size_t)st * STGB + (size_t)NT * TILEB);
    };

    const int tid = threadIdx.x;
    const int m0 = blockIdx.y * BM;
    const int n0 = blockIdx.x * BN;
    const int warp = tid >> 5, lane = tid & 31;
    const int wm = (warp >> 1) * 32;  // 4 warps along M
    const int wn = (warp & 1) * 64;   // 2 warps along N

    float acc[2][8][4];
#pragma unroll
    for (int i = 0; i < 2; i++)
#pragma unroll
        for (int j = 0; j < 8; j++)
#pragma unroll
            for (int q = 0; q < 4; q++) acc[i][j][q] = 0.f;

    auto load_stage = [&](int s) {
        const int st = s % 3;
        const int k0 = s * BK;
#pragma unroll
        for (int i = 0; i < 2; i++) {
            int c = i * 256 + tid;          // 0..511
            int row = c >> 2;               // 0..127
            int col = (c & 3) * 8;
            uint32_t d = (uint32_t)(row * KST + col) * 2;
            size_t offA = (size_t)(m0 + row) * HD + k0 + col;
            cp16(smem_u32(tA(st, 0)) + d, A1 + offA);
            if (NT == 2) cp16(smem_u32(tA(st, 1)) + d, A2 + offA);
            size_t offB = (size_t)(n0 + row) * HD + k0 + col;
            cp16(smem_u32(tB(st)) + d, Bp + offB);
        }
        asm volatile("cp.async.commit_group;\n");
    };

    load_stage(0);
    load_stage(1);

    for (int s = 0; s < 16; ++s) {
        const int st = s % 3;
        if (s == 15) asm volatile("cp.async.wait_group 0;\n");
        else         asm volatile("cp.async.wait_group 1;\n");
        __syncthreads();
        if (s + 2 < 16) load_stage(s + 2);

        const fp16* Bt = tB(st);
#pragma unroll
        for (int kk = 0; kk < BK; kk += 16) {
            uint32_t bF[4][4];
#pragma unroll
            for (int nb = 0; nb < 4; nb++)
                ldm4(bF[nb], smem_u32(Bt + (wn + nb * 16 + (lane & 7) + ((lane >> 4) << 3)) * KST
                                         + kk + (((lane >> 3) & 1) << 3)));
#pragma unroll
            for (int t = 0; t < NT; t++) {
                const fp16* At = tA(st, t);
                uint32_t aF[2][4];
#pragma unroll
                for (int mi = 0; mi < 2; mi++)
                    ldm4(aF[mi], smem_u32(At + (wm + mi * 16 + (lane & 15)) * KST
                                             + kk + ((lane >> 4) << 3)));
#pragma unroll
                for (int mi = 0; mi < 2; mi++)
#pragma unroll
                    for (int ni = 0; ni < 8; ni++)
                        mma16816(acc[mi][ni], aF[mi], bF[ni >> 1][(ni & 1) * 2],
                                 bF[ni >> 1][(ni & 1) * 2 + 1]);
            }
        }
    }

    // epilogue: write fp32 C
#pragma unroll
    for (int mi = 0; mi < 2; mi++)
#pragma unroll
        for (int ni = 0; ni < 8; ni++) {
            int r = m0 + wm + mi * 16 + (lane >> 2);
            int c = n0 + wn + ni * 8 + (lane & 3) * 2;
            *reinterpret_cast<float2*>(&C[(size_t)r * N + c]) =
                make_float2(acc[mi][ni][0], acc[mi][ni][1]);
            *reinterpret_cast<float2*>(&C[(size_t)(r + 8) * N + c]) =
                make_float2(acc[mi][ni][2], acc[mi][ni][3]);
        }
}

#define SMEM_G1 (3 * 2 * TILEB)   // 61440
#define SMEM_G2 (3 * 3 * TILEB)   // 92160

// ---------------- LN over g_pre -> u (fp16 hi/lo) ----------------
__global__ void ln_u_kernel(const float* __restrict__ bias, const float* __restrict__ gamma,
                            const float* __restrict__ beta) {
    int row = blockIdx.x * 8 + (threadIdx.x >> 5);
    int lane = threadIdx.x & 31;
    const float* p = g_pre + (size_t)row * HD;
    float v[16];
    float sm = 0.f, sq = 0.f;
#pragma unroll
    for (int i = 0; i < 4; i++) {
        int c = i * 128 + lane * 4;
        float4 x4 = *reinterpret_cast<const float4*>(p + c);
        float4 b4 = *reinterpret_cast<const float4*>(bias + c);
        float t0 = x4.x + b4.x, t1 = x4.y + b4.y, t2 = x4.z + b4.z, t3 = x4.w + b4.w;
        v[i * 4 + 0] = t0; v[i * 4 + 1] = t1; v[i * 4 + 2] = t2; v[i * 4 + 3] = t3;
        sm += t0 + t1 + t2 + t3;
        sq += t0 * t0 + t1 * t1 + t2 * t2 + t3 * t3;
    }
#pragma unroll
    for (int o = 16; o; o >>= 1) {
        sm += __shfl_xor_sync(0xffffffffu, sm, o);
        sq += __shfl_xor_sync(0xffffffffu, sq, o);
    }
    float mean = sm * (1.f / HD);
    float inv = rsqrtf(fmaxf(sq * (1.f / HD) - mean * mean, 0.f) + 1e-5f);
#pragma unroll
    for (int i = 0; i < 4; i++) {
        int c = i * 128 + lane * 4;
        float4 g4 = *reinterpret_cast<const float4*>(gamma + c);
        float4 b4 = *reinterpret_cast<const float4*>(beta + c);
        float u0 = (v[i * 4 + 0] - mean) * inv * g4.x + b4.x;
        float u1 = (v[i * 4 + 1] - mean) * inv * g4.y + b4.y;
        float u2 = (v[i * 4 + 2] - mean) * inv * g4.z + b4.z;
        float u3 = (v[i * 4 + 3] - mean) * inv * g4.w + b4.w;
        size_t idx = (size_t)row * HD + c;
        split_store2(g_u1 + idx, g_u2 + idx, u0, u1);
        split_store2(g_u1 + idx + 2, g_u2 + idx + 2, u2, u3);
    }
}

// ---------------- epilogue 1: z, s, t ----------------
__global__ void epi1_kernel(const float* __restrict__ s_prev, const float* __restrict__ bz,
                            const float* __restrict__ glz, const float* __restrict__ blz,
                            const float* __restrict__ bk, const float* __restrict__ bv,
                            const float* __restrict__ bd, float* __restrict__ out_s) {
    int row = blockIdx.x * 8 + (threadIdx.x >> 5);
    int lane = threadIdx.x & 31;
    const float* Pr = g_P + (size_t)row * (4 * HD);
    float zp[16];
    float sm = 0.f, sq = 0.f;
#pragma unroll
    for (int i = 0; i < 4; i++) {
        int c = i * 128 + lane * 4;
        float4 z4 = *reinterpret_cast<const float4*>(Pr + c);
        float4 b4 = *reinterpret_cast<const float4*>(bz + c);
        float t0 = z4.x + b4.x, t1 = z4.y + b4.y, t2 = z4.z + b4.z, t3 = z4.w + b4.w;
        zp[i * 4 + 0] = t0; zp[i * 4 + 1] = t1; zp[i * 4 + 2] = t2; zp[i * 4 + 3] = t3;
        sm += t0 + t1 + t2 + t3;
        sq += t0 * t0 + t1 * t1 + t2 * t2 + t3 * t3;
    }
#pragma unroll
    for (int o = 16; o; o >>= 1) {
        sm += __shfl_xor_sync(0xffffffffu, sm, o);
        sq += __shfl_xor_sync(0xffffffffu, sq, o);
    }
    float mean = sm * (1.f / HD);
    float inv = rsqrtf(fmaxf(sq * (1.f / HD) - mean * mean, 0.f) + 1e-5f);
#pragma unroll
    for (int i = 0; i < 4; i++) {
        int c = i * 128 + lane * 4;
        size_t idx = (size_t)row * HD + c;
        float4 g4 = *reinterpret_cast<const float4*>(glz + c);
        float4 bb4 = *reinterpret_cast<const float4*>(blz + c);
        float z0 = sigf((zp[i * 4 + 0] - mean) * inv * g4.x + bb4.x);
        float z1 = sigf((zp[i * 4 + 1] - mean) * inv * g4.y + bb4.y);
        float z2 = sigf((zp[i * 4 + 2] - mean) * inv * g4.z + bb4.z);
        float z3 = sigf((zp[i * 4 + 3] - mean) * inv * g4.w + bb4.w);

        float4 k4 = *reinterpret_cast<const float4*>(Pr + HD + c);
        float4 bk4 = *reinterpret_cast<const float4*>(bk + c);
        float4 v4 = *reinterpret_cast<const float4*>(Pr + 2 * HD + c);
        float4 bv4 = *reinterpret_cast<const float4*>(bv + c);
        float4 d4 = *reinterpret_cast<const float4*>(Pr + 3 * HD + c);
        float4 bd4 = *reinterpret_cast<const float4*>(bd + c);
        float4 sp = *reinterpret_cast<const float4*>(s_prev + idx);

        float kk0 = k4.x + bk4.x, kk1 = k4.y + bk4.y, kk2 = k4.z + bk4.z, kk3 = k4.w + bk4.w;
        float vv0 = v4.x + bv4.x, vv1 = v4.y + bv4.y, vv2 = v4.z + bv4.z, vv3 = v4.w + bv4.w;
        float dc0 = sigf(d4.x + bd4.x), dc1 = sigf(d4.y + bd4.y);
        float dc2 = sigf(d4.z + bd4.z), dc3 = sigf(d4.w + bd4.w);
        float s0 = dc0 * sp.x + kk0 * vv0;
        float s1 = dc1 * sp.y + kk1 * vv1;
        float s2 = dc2 * sp.z + kk2 * vv2;
        float s3 = dc3 * sp.w + kk3 * vv3;
        *reinterpret_cast<float4*>(out_s + idx) = make_float4(s0, s1, s2, s3);

        __half2 uh0 = *reinterpret_cast<const __half2*>(g_u1 + idx);
        __half2 ul0 = *reinterpret_cast<const __half2*>(g_u2 + idx);
        __half2 uh1 = *reinterpret_cast<const __half2*>(g_u1 + idx + 2);
        __half2 ul1 = *reinterpret_cast<const __half2*>(g_u2 + idx + 2);
        float u0 = __half2float(uh0.x) + __half2float(ul0.x);
        float u1 = __half2float(uh0.y) + __half2float(ul0.y);
        float u2 = __half2float(uh1.x) + __half2float(ul1.x);
        float u3 = __half2float(uh1.y) + __half2float(ul1.y);
        split_store2(g_t1 + idx, g_t2 + idx, u0 + s0, u1 + s1);
        split_store2(g_t1 + idx + 2, g_t2 + idx + 2, u2 + s2, u3 + s3);
        *reinterpret_cast<float4*>(&g_z[idx]) = make_float4(z0, z1, z2, z3);
    }
}

// ---------------- epilogue 2: h ----------------
__global__ void epi2_kernel(const float* __restrict__ h_prev, const float* __restrict__ bh,
                            const float* __restrict__ glh, const float* __restrict__ blh,
                            float* __restrict__ out_h) {
    int row = blockIdx.x * 8 + (threadIdx.x >> 5);
    int lane = threadIdx.x & 31;
    const float* p = g_pre + (size_t)row * HD;
    float v[16];
    float sm = 0.f, sq = 0.f;
#pragma unroll
    for (int i = 0; i < 4; i++) {
        int c = i * 128 + lane * 4;
        float4 x4 = *reinterpret_cast<const float4*>(p + c);
        float4 b4 = *reinterpret_cast<const float4*>(bh + c);
        float t0 = x4.x + b4.x, t1 = x4.y + b4.y, t2 = x4.z + b4.z, t3 = x4.w + b4.w;
        v[i * 4 + 0] = t0; v[i * 4 + 1] = t1; v[i * 4 + 2] = t2; v[i * 4 + 3] = t3;
        sm += t0 + t1 + t2 + t3;
        sq += t0 * t0 + t1 * t1 + t2 * t2 + t3 * t3;
    }
#pragma unroll
    for (int o = 16; o; o >>= 1) {
        sm += __shfl_xor_sync(0xffffffffu, sm, o);
        sq += __shfl_xor_sync(0xffffffffu, sq, o);
    }
    float mean = sm * (1.f / HD);
    float inv = rsqrtf(fmaxf(sq * (1.f / HD) - mean * mean, 0.f) + 1e-5f);
#pragma unroll
    for (int i = 0; i < 4; i++) {
        int c = i * 128 + lane * 4;
        size_t idx = (size_t)row * HD + c;
        float4 g4 = *reinterpret_cast<const float4*>(glh + c);
        float4 b4 = *reinterpret_cast<const float4*>(blh + c);
        float c0 = tanhf((v[i * 4 + 0] - mean) * inv * g4.x + b4.x);
        float c1 = tanhf((v[i * 4 + 1] - mean) * inv * g4.y + b4.y);
        float c2 = tanhf((v[i * 4 + 2] - mean) * inv * g4.z + b4.z);
        float c3 = tanhf((v[i * 4 + 3] - mean) * inv * g4.w + b4.w);
        float4 z4 = *reinterpret_cast<const float4*>(&g_z[idx]);
        float4 hp = *reinterpret_cast<const float4*>(h_prev + idx);
        float h0 = (1.f - z4.x) * c0 + z4.x * hp.x;
        float h1 = (1.f - z4.y) * c1 + z4.y * hp.y;
        float h2 = (1.f - z4.z) * c2 + z4.z * hp.z;
        float h3 = (1.f - z4.w) * c3 + z4.w * hp.w;
        *reinterpret_cast<float4*>(out_h + idx) = make_float4(h0, h1, h2, h3);
    }
}

// ---------------- launch ----------------
extern "C" void kernel_launch(void* const* d_in, const int* in_sizes, int n_in,
                              void* d_out, int out_size) {
    const float* x       = (const float*)d_in[0];
    const float* h_prev  = (const float*)d_in[1];
    const float* s_prev  = (const float*)d_in[2];
    const float* W_in    = (const float*)d_in[3];
    const float* b_in    = (const float*)d_in[4];
    const float* g_ln_in = (const float*)d_in[5];
    const float* b_ln_in = (const float*)d_in[6];
    const float* g_ln_z  = (const float*)d_in[9];
    const float* b_ln_z  = (const float*)d_in[10];
    const float* g_ln_h  = (const float*)d_in[11];
    const float* b_ln_h  = (const float*)d_in[12];
    const float* W_z     = (const float*)d_in[15];
    const float* b_z     = (const float*)d_in[16];
    const float* W_k     = (const float*)d_in[17];
    const float* b_k     = (const float*)d_in[18];
    const float* W_v     = (const float*)d_in[19];
    const float* b_v     = (const float*)d_in[20];
    const float* W_h     = (const float*)d_in[21];
    const float* b_h     = (const float*)d_in[22];
    const float* W_d     = (const float*)d_in[23];
    const float* b_d     = (const float*)d_in[24];

    float* out_h = (float*)d_out;
    float* out_s = out_h + (size_t)BATCH * HD;

    cudaFuncSetAttribute(gemm_kernel<0>, cudaFuncAttributeMaxDynamicSharedMemorySize, SMEM_G1);
    cudaFuncSetAttribute(gemm_kernel<1>, cudaFuncAttributeMaxDynamicSharedMemorySize, SMEM_G2);
    cudaFuncSetAttribute(gemm_kernel<2>, cudaFuncAttributeMaxDynamicSharedMemorySize, SMEM_G2);

    prep_weights<<<(6 * HD * HD + 255) / 256, 256>>>(W_in, W_z, W_k, W_v, W_d, W_h);
    conv_x_kernel<<<BATCH * HD / 4 / 256, 256>>>(x);

    gemm_kernel<0><<<dim3(HD / BN, BATCH / BM), 256, SMEM_G1>>>();
    ln_u_kernel<<<BATCH / 8, 256>>>(b_in, g_ln_in, b_ln_in);

    gemm_kernel<1><<<dim3(4 * HD / BN, BATCH / BM), 256, SMEM_G2>>>();
    epi1_kernel<<<BATCH / 8, 256>>>(s_prev, b_z, g_ln_z, b_ln_z, b_k, b_v, b_d, out_s);

    gemm_kernel<2><<<dim3(HD / BN, BATCH / BM), 256, SMEM_G2>>>();
    epi2_kernel<<<BATCH / 8, 256>>>(h_prev, b_h, g_ln_h, b_ln_h, out_h);
}

// round 15
// speedup vs baseline: 1.5759x; 1.3156x over previous
#include <cuda_runtime.h>
#include <cuda_fp16.h>
#include <cstdint>

#define BATCH 32768
#define HD 512
typedef __half fp16;

// ---------------- device scratch (no allocations allowed) ----------------
__device__ fp16 g_x1[BATCH * HD];
__device__ fp16 g_u1[BATCH * HD], g_u2[BATCH * HD];
__device__ fp16 g_t1[BATCH * HD], g_t2[BATCH * HD];
__device__ float g_pre[BATCH * HD];               // GEMM1 out, reused for GEMM3 out
__device__ float g_P[(size_t)BATCH * 4 * HD];     // z_pre | k | v | d_pre
__device__ float g_z[BATCH * HD];
__device__ fp16 g_W_in[HD * HD];
__device__ fp16 g_W_cat[4 * HD * HD];
__device__ fp16 g_W_h[HD * HD];

// ---------------- helpers ----------------
__device__ __forceinline__ uint32_t smem_u32(const void* p) {
    return (uint32_t)__cvta_generic_to_shared(p);
}
__device__ __forceinline__ void cp16(uint32_t dst, const void* src) {
    asm volatile("cp.async.cg.shared.global [%0], [%1], 16;\n" :: "r"(dst), "l"(src));
}
__device__ __forceinline__ void ldm4(uint32_t (&r)[4], uint32_t addr) {
    asm volatile("ldmatrix.sync.aligned.m8n8.x4.shared.b16 {%0,%1,%2,%3}, [%4];\n"
                 : "=r"(r[0]), "=r"(r[1]), "=r"(r[2]), "=r"(r[3]) : "r"(addr));
}
__device__ __forceinline__ void mma16816(float (&d)[4], const uint32_t (&a)[4],
                                         uint32_t b0, uint32_t b1) {
    asm volatile("mma.sync.aligned.m16n8k16.row.col.f32.f16.f16.f32 "
                 "{%0,%1,%2,%3}, {%4,%5,%6,%7}, {%8,%9}, {%0,%1,%2,%3};\n"
                 : "+f"(d[0]), "+f"(d[1]), "+f"(d[2]), "+f"(d[3])
                 : "r"(a[0]), "r"(a[1]), "r"(a[2]), "r"(a[3]), "r"(b0), "r"(b1));
}
__device__ __forceinline__ float sigf(float x) { return 1.0f / (1.0f + __expf(-x)); }

__device__ __forceinline__ void split_store2(fp16* hi, fp16* lo, float a, float b) {
    fp16 ha = __float2half_rn(a);
    fp16 hb = __float2half_rn(b);
    *reinterpret_cast<__half2*>(hi) = __halves2half2(ha, hb);
    fp16 la = __float2half_rn(a - __half2float(ha));
    fp16 lb = __float2half_rn(b - __half2float(hb));
    *reinterpret_cast<__half2*>(lo) = __halves2half2(la, lb);
}

// ---------------- weight prep: transpose to [N][K] fp16 ----------------
__global__ void prep_weights(const float* __restrict__ W_in, const float* __restrict__ W_z,
                             const float* __restrict__ W_k, const float* __restrict__ W_v,
                             const float* __restrict__ W_d, const float* __restrict__ W_h) {
    int idx = blockIdx.x * 256 + threadIdx.x;
    if (idx >= 6 * HD * HD) return;
    int mat = idx / (HD * HD);
    int e = idx % (HD * HD);
    int k = e / HD, n = e % HD;
    const float* W;
    fp16* D;
    int dst;
    if (mat == 0) {
        W = W_in; D = g_W_in; dst = n * HD + k;
    } else if (mat <= 4) {
        W = (mat == 1) ? W_z : (mat == 2) ? W_k : (mat == 3) ? W_v : W_d;
        D = g_W_cat; dst = ((mat - 1) * HD + n) * HD + k;
    } else {
        W = W_h; D = g_W_h; dst = n * HD + k;
    }
    D[dst] = __float2half_rn(W[e]);   // W[k][n], coalesced read over n
}

// ---------------- x -> single fp16 ----------------
__global__ void conv_x_kernel(const float* __restrict__ x) {
    int i = blockIdx.x * 256 + threadIdx.x;  // float4 index
    float4 v = reinterpret_cast<const float4*>(x)[i];
    __half2 a = __halves2half2(__float2half_rn(v.x), __float2half_rn(v.y));
    __half2 b = __halves2half2(__float2half_rn(v.z), __float2half_rn(v.w));
    *reinterpret_cast<__half2*>(g_x1 + (size_t)i * 4) = a;
    *reinterpret_cast<__half2*>(g_x1 + (size_t)i * 4 + 2) = b;
}

// ---------------- split-fp16 GEMM: C[M,N] = A[M,512] @ W[512,N] ----------------
// Round-6 proven structure: 2-stage double buffer, two syncs per stage,
// separate compute passes per A term.
// WHICH==0: 1 term (x fp16). WHICH==1: 2 terms (u), N=2048. WHICH==2: 2 terms (t).
#define BM 128
#define BN 128
#define BK 32
#define KST 40                         // padded row stride (fp16) = 80 bytes
#define TILEB (BM * KST * 2)           // 10240 bytes per [128][40] fp16 tile
#define NSTG 16                        // 512 / 32

template <int WHICH>
__global__ void __launch_bounds__(256, 2) gemm2_kernel() {
    constexpr int NT = (WHICH == 0) ? 1 : 2;         // A terms
    constexpr int TPS = NT + 1;                      // tiles per stage
    const fp16* A1 = (WHICH == 0) ? g_x1 : (WHICH == 1) ? g_u1 : g_t1;
    const fp16* A2 = (WHICH == 0) ? g_x1 : (WHICH == 1) ? g_u2 : g_t2;  // unused for 0
    const fp16* Bp = (WHICH == 0) ? g_W_in : (WHICH == 1) ? g_W_cat : g_W_h;
    float* C = (WHICH == 1) ? g_P : g_pre;
    const int N = (WHICH == 1) ? 4 * HD : HD;

    extern __shared__ __align__(16) char sm[];
    auto tile = [&](int stage, int sel) -> fp16* {   // sel: 0..NT-1 = A terms, NT = B
        return reinterpret_cast<fp16*>(sm + (size_t)(stage * TPS + sel) * TILEB);
    };

    const int tid = threadIdx.x;
    const int m0 = blockIdx.y * BM;
    const int n0 = blockIdx.x * BN;
    const int warp = tid >> 5, lane = tid & 31;
    const int wm = (warp >> 1) * 32;  // 4 warps along M
    const int wn = (warp & 1) * 64;   // 2 warps along N

    float acc[2][8][4];
#pragma unroll
    for (int i = 0; i < 2; i++)
#pragma unroll
        for (int j = 0; j < 8; j++)
#pragma unroll
            for (int q = 0; q < 4; q++) acc[i][j][q] = 0.f;

    auto load_stage = [&](int s) {
        const int st = s & 1;
        const int k0 = s * BK;
        fp16* a1 = tile(st, 0);
        fp16* bb = tile(st, NT);
#pragma unroll
        for (int i = 0; i < 2; i++) {
            int c = i * 256 + tid;          // 0..511
            int row = c >> 2;               // 0..127
            int col = (c & 3) * 8;          // fp16 col offset within 32
            uint32_t d = (uint32_t)(row * KST + col) * 2;  // byte offset
            size_t offA = (size_t)(m0 + row) * HD + k0 + col;
            cp16(smem_u32(a1) + d, A1 + offA);
            if (NT == 2) cp16(smem_u32(tile(st, 1)) + d, A2 + offA);
            size_t offB = (size_t)(n0 + row) * HD + k0 + col;
            cp16(smem_u32(bb) + d, Bp + offB);
        }
        asm volatile("cp.async.commit_group;\n");
    };

    auto compute_pass = [&](const fp16* At, const fp16* Bt) {
#pragma unroll
        for (int kk = 0; kk < BK; kk += 16) {
            uint32_t aF[2][4];
#pragma unroll
            for (int mi = 0; mi < 2; mi++) {
                uint32_t ad = smem_u32(At + (wm + mi * 16 + (lane & 15)) * KST
                                          + kk + ((lane >> 4) << 3));
                ldm4(aF[mi], ad);
            }
            uint32_t bF[4][4];
#pragma unroll
            for (int nb = 0; nb < 4; nb++) {
                uint32_t bd = smem_u32(Bt + (wn + nb * 16 + (lane & 7) + ((lane >> 4) << 3)) * KST
                                          + kk + (((lane >> 3) & 1) << 3));
                ldm4(bF[nb], bd);
            }
#pragma unroll
            for (int mi = 0; mi < 2; mi++)
#pragma unroll
                for (int ni = 0; ni < 8; ni++)
                    mma16816(acc[mi][ni], aF[mi], bF[ni >> 1][(ni & 1) * 2],
                             bF[ni >> 1][(ni & 1) * 2 + 1]);
        }
    };

    load_stage(0);
    load_stage(1);

    for (int s = 0; s < NSTG; ++s) {
        const int st = s & 1;
        if (s == NSTG - 1) asm volatile("cp.async.wait_group 0;\n");
        else               asm volatile("cp.async.wait_group 1;\n");
        __syncthreads();
        compute_pass(tile(st, 0), tile(st, NT));               // A1 * B
        if (NT == 2) compute_pass(tile(st, 1), tile(st, NT));  // A2 * B
        __syncthreads();
        if (s + 2 < NSTG) load_stage(s + 2);
    }

    // epilogue: write fp32 C
#pragma unroll
    for (int mi = 0; mi < 2; mi++)
#pragma unroll
        for (int ni = 0; ni < 8; ni++) {
            int r = m0 + wm + mi * 16 + (lane >> 2);
            int c = n0 + wn + ni * 8 + (lane & 3) * 2;
            *reinterpret_cast<float2*>(&C[(size_t)r * N + c]) =
                make_float2(acc[mi][ni][0], acc[mi][ni][1]);
            *reinterpret_cast<float2*>(&C[(size_t)(r + 8) * N + c]) =
                make_float2(acc[mi][ni][2], acc[mi][ni][3]);
        }
}

#define SMEM_G1 (4 * TILEB)   // 40960: 2 stages * (A1, B)
#define SMEM_G2 (6 * TILEB)   // 61440: 2 stages * (A1, A2, B)

// ---------------- LN over g_pre -> u (fp16 hi/lo) ----------------
__global__ void ln_u_kernel(const float* __restrict__ bias, const float* __restrict__ gamma,
                            const float* __restrict__ beta) {
    int row = blockIdx.x * 8 + (threadIdx.x >> 5);
    int lane = threadIdx.x & 31;
    const float* p = g_pre + (size_t)row * HD;
    float v[16];
    float sm = 0.f, sq = 0.f;
#pragma unroll
    for (int i = 0; i < 4; i++) {
        int c = i * 128 + lane * 4;
        float4 x4 = *reinterpret_cast<const float4*>(p + c);
        float4 b4 = *reinterpret_cast<const float4*>(bias + c);
        float t0 = x4.x + b4.x, t1 = x4.y + b4.y, t2 = x4.z + b4.z, t3 = x4.w + b4.w;
        v[i * 4 + 0] = t0; v[i * 4 + 1] = t1; v[i * 4 + 2] = t2; v[i * 4 + 3] = t3;
        sm += t0 + t1 + t2 + t3;
        sq += t0 * t0 + t1 * t1 + t2 * t2 + t3 * t3;
    }
#pragma unroll
    for (int o = 16; o; o >>= 1) {
        sm += __shfl_xor_sync(0xffffffffu, sm, o);
        sq += __shfl_xor_sync(0xffffffffu, sq, o);
    }
    float mean = sm * (1.f / HD);
    float inv = rsqrtf(fmaxf(sq * (1.f / HD) - mean * mean, 0.f) + 1e-5f);
#pragma unroll
    for (int i = 0; i < 4; i++) {
        int c = i * 128 + lane * 4;
        float4 g4 = *reinterpret_cast<const float4*>(gamma + c);
        float4 b4 = *reinterpret_cast<const float4*>(beta + c);
        float u0 = (v[i * 4 + 0] - mean) * inv * g4.x + b4.x;
        float u1 = (v[i * 4 + 1] - mean) * inv * g4.y + b4.y;
        float u2 = (v[i * 4 + 2] - mean) * inv * g4.z + b4.z;
        float u3 = (v[i * 4 + 3] - mean) * inv * g4.w + b4.w;
        size_t idx = (size_t)row * HD + c;
        split_store2(g_u1 + idx, g_u2 + idx, u0, u1);
        split_store2(g_u1 + idx + 2, g_u2 + idx + 2, u2, u3);
    }
}

// ---------------- epilogue 1: z, s, t ----------------
__global__ void epi1_kernel(const float* __restrict__ s_prev, const float* __restrict__ bz,
                            const float* __restrict__ glz, const float* __restrict__ blz,
                            const float* __restrict__ bk, const float* __restrict__ bv,
                            const float* __restrict__ bd, float* __restrict__ out_s) {
    int row = blockIdx.x * 8 + (threadIdx.x >> 5);
    int lane = threadIdx.x & 31;
    const float* Pr = g_P + (size_t)row * (4 * HD);
    float zp[16];
    float sm = 0.f, sq = 0.f;
#pragma unroll
    for (int i = 0; i < 4; i++) {
        int c = i * 128 + lane * 4;
        float4 z4 = *reinterpret_cast<const float4*>(Pr + c);
        float4 b4 = *reinterpret_cast<const float4*>(bz + c);
        float t0 = z4.x + b4.x, t1 = z4.y + b4.y, t2 = z4.z + b4.z, t3 = z4.w + b4.w;
        zp[i * 4 + 0] = t0; zp[i * 4 + 1] = t1; zp[i * 4 + 2] = t2; zp[i * 4 + 3] = t3;
        sm += t0 + t1 + t2 + t3;
        sq += t0 * t0 + t1 * t1 + t2 * t2 + t3 * t3;
    }
#pragma unroll
    for (int o = 16; o; o >>= 1) {
        sm += __shfl_xor_sync(0xffffffffu, sm, o);
        sq += __shfl_xor_sync(0xffffffffu, sq, o);
    }
    float mean = sm * (1.f / HD);
    float inv = rsqrtf(fmaxf(sq * (1.f / HD) - mean * mean, 0.f) + 1e-5f);
#pragma unroll
    for (int i = 0; i < 4; i++) {
        int c = i * 128 + lane * 4;
        size_t idx = (size_t)row * HD + c;
        float4 g4 = *reinterpret_cast<const float4*>(glz + c);
        float4 bb4 = *reinterpret_cast<const float4*>(blz + c);
        float z0 = sigf((zp[i * 4 + 0] - mean) * inv * g4.x + bb4.x);
        float z1 = sigf((zp[i * 4 + 1] - mean) * inv * g4.y + bb4.y);
        float z2 = sigf((zp[i * 4 + 2] - mean) * inv * g4.z + bb4.z);
        float z3 = sigf((zp[i * 4 + 3] - mean) * inv * g4.w + bb4.w);

        float4 k4 = *reinterpret_cast<const float4*>(Pr + HD + c);
        float4 bk4 = *reinterpret_cast<const float4*>(bk + c);
        float4 v4 = *reinterpret_cast<const float4*>(Pr + 2 * HD + c);
        float4 bv4 = *reinterpret_cast<const float4*>(bv + c);
        float4 d4 = *reinterpret_cast<const float4*>(Pr + 3 * HD + c);
        float4 bd4 = *reinterpret_cast<const float4*>(bd + c);
        float4 sp = *reinterpret_cast<const float4*>(s_prev + idx);

        float kk0 = k4.x + bk4.x, kk1 = k4.y + bk4.y, kk2 = k4.z + bk4.z, kk3 = k4.w + bk4.w;
        float vv0 = v4.x + bv4.x, vv1 = v4.y + bv4.y, vv2 = v4.z + bv4.z, vv3 = v4.w + bv4.w;
        float dc0 = sigf(d4.x + bd4.x), dc1 = sigf(d4.y + bd4.y);
        float dc2 = sigf(d4.z + bd4.z), dc3 = sigf(d4.w + bd4.w);
        float s0 = dc0 * sp.x + kk0 * vv0;
        float s1 = dc1 * sp.y + kk1 * vv1;
        float s2 = dc2 * sp.z + kk2 * vv2;
        float s3 = dc3 * sp.w + kk3 * vv3;
        *reinterpret_cast<float4*>(out_s + idx) = make_float4(s0, s1, s2, s3);

        __half2 uh0 = *reinterpret_cast<const __half2*>(g_u1 + idx);
        __half2 ul0 = *reinterpret_cast<const __half2*>(g_u2 + idx);
        __half2 uh1 = *reinterpret_cast<const __half2*>(g_u1 + idx + 2);
        __half2 ul1 = *reinterpret_cast<const __half2*>(g_u2 + idx + 2);
        float u0 = __half2float(uh0.x) + __half2float(ul0.x);
        float u1 = __half2float(uh0.y) + __half2float(ul0.y);
        float u2 = __half2float(uh1.x) + __half2float(ul1.x);
        float u3 = __half2float(uh1.y) + __half2float(ul1.y);
        split_store2(g_t1 + idx, g_t2 + idx, u0 + s0, u1 + s1);
        split_store2(g_t1 + idx + 2, g_t2 + idx + 2, u2 + s2, u3 + s3);
        *reinterpret_cast<float4*>(&g_z[idx]) = make_float4(z0, z1, z2, z3);
    }
}

// ---------------- epilogue 2: h ----------------
__global__ void epi2_kernel(const float* __restrict__ h_prev, const float* __restrict__ bh,
                            const float* __restrict__ glh, const float* __restrict__ blh,
                            float* __restrict__ out_h) {
    int row = blockIdx.x * 8 + (threadIdx.x >> 5);
    int lane = threadIdx.x & 31;
    const float* p = g_pre + (size_t)row * HD;
    float v[16];
    float sm = 0.f, sq = 0.f;
#pragma unroll
    for (int i = 0; i < 4; i++) {
        int c = i * 128 + lane * 4;
        float4 x4 = *reinterpret_cast<const float4*>(p + c);
        float4 b4 = *reinterpret_cast<const float4*>(bh + c);
        float t0 = x4.x + b4.x, t1 = x4.y + b4.y, t2 = x4.z + b4.z, t3 = x4.w + b4.w;
        v[i * 4 + 0] = t0; v[i * 4 + 1] = t1; v[i * 4 + 2] = t2; v[i * 4 + 3] = t3;
        sm += t0 + t1 + t2 + t3;
        sq += t0 * t0 + t1 * t1 + t2 * t2 + t3 * t3;
    }
#pragma unroll
    for (int o = 16; o; o >>= 1) {
        sm += __shfl_xor_sync(0xffffffffu, sm, o);
        sq += __shfl_xor_sync(0xffffffffu, sq, o);
    }
    float mean = sm * (1.f / HD);
    float inv = rsqrtf(fmaxf(sq * (1.f / HD) - mean * mean, 0.f) + 1e-5f);
#pragma unroll
    for (int i = 0; i < 4; i++) {
        int c = i * 128 + lane * 4;
        size_t idx = (size_t)row * HD + c;
        float4 g4 = *reinterpret_cast<const float4*>(glh + c);
        float4 b4 = *reinterpret_cast<const float4*>(blh + c);
        float c0 = tanhf((v[i * 4 + 0] - mean) * inv * g4.x + b4.x);
        float c1 = tanhf((v[i * 4 + 1] - mean) * inv * g4.y + b4.y);
        float c2 = tanhf((v[i * 4 + 2] - mean) * inv * g4.z + b4.z);
        float c3 = tanhf((v[i * 4 + 3] - mean) * inv * g4.w + b4.w);
        float4 z4 = *reinterpret_cast<const float4*>(&g_z[idx]);
        float4 hp = *reinterpret_cast<const float4*>(h_prev + idx);
        float h0 = (1.f - z4.x) * c0 + z4.x * hp.x;
        float h1 = (1.f - z4.y) * c1 + z4.y * hp.y;
        float h2 = (1.f - z4.z) * c2 + z4.z * hp.z;
        float h3 = (1.f - z4.w) * c3 + z4.w * hp.w;
        *reinterpret_cast<float4*>(out_h + idx) = make_float4(h0, h1, h2, h3);
    }
}

// ---------------- launch ----------------
extern "C" void kernel_launch(void* const* d_in, const int* in_sizes, int n_in,
                              void* d_out, int out_size) {
    const float* x       = (const float*)d_in[0];
    const float* h_prev  = (const float*)d_in[1];
    const float* s_prev  = (const float*)d_in[2];
    const float* W_in    = (const float*)d_in[3];
    const float* b_in    = (const float*)d_in[4];
    const float* g_ln_in = (const float*)d_in[5];
    const float* b_ln_in = (const float*)d_in[6];
    const float* g_ln_z  = (const float*)d_in[9];
    const float* b_ln_z  = (const float*)d_in[10];
    const float* g_ln_h  = (const float*)d_in[11];
    const float* b_ln_h  = (const float*)d_in[12];
    const float* W_z     = (const float*)d_in[15];
    const float* b_z     = (const float*)d_in[16];
    const float* W_k     = (const float*)d_in[17];
    const float* b_k     = (const float*)d_in[18];
    const float* W_v     = (const float*)d_in[19];
    const float* b_v     = (const float*)d_in[20];
    const float* W_h     = (const float*)d_in[21];
    const float* b_h     = (const float*)d_in[22];
    const float* W_d     = (const float*)d_in[23];
    const float* b_d     = (const float*)d_in[24];

    float* out_h = (float*)d_out;
    float* out_s = out_h + (size_t)BATCH * HD;

    cudaFuncSetAttribute(gemm2_kernel<0>, cudaFuncAttributeMaxDynamicSharedMemorySize, SMEM_G1);
    cudaFuncSetAttribute(gemm2_kernel<1>, cudaFuncAttributeMaxDynamicSharedMemorySize, SMEM_G2);
    cudaFuncSetAttribute(gemm2_kernel<2>, cudaFuncAttributeMaxDynamicSharedMemorySize, SMEM_G2);

    prep_weights<<<(6 * HD * HD + 255) / 256, 256>>>(W_in, W_z, W_k, W_v, W_d, W_h);
    conv_x_kernel<<<BATCH * HD / 4 / 256, 256>>>(x);

    gemm2_kernel<0><<<dim3(HD / BN, BATCH / BM), 256, SMEM_G1>>>();
    ln_u_kernel<<<BATCH / 8, 256>>>(b_in, g_ln_in, b_ln_in);

    gemm2_kernel<1><<<dim3(4 * HD / BN, BATCH / BM), 256, SMEM_G2>>>();
    epi1_kernel<<<BATCH / 8, 256>>>(s_prev, b_z, g_ln_z, b_ln_z, b_k, b_v, b_d, out_s);

    gemm2_kernel<2><<<dim3(HD / BN, BATCH / BM), 256, SMEM_G2>>>();
    epi2_kernel<<<BATCH / 8, 256>>>(h_prev, b_h, g_ln_h, b_ln_h, out_h);
}

// round 17
// speedup vs baseline: 1.7285x; 1.0968x over previous
#include <cuda_runtime.h>
#include <cuda_fp16.h>
#include <cstdint>

#define BATCH 32768
#define HD 512
typedef __half fp16;

// ---------------- device scratch (no allocations allowed) ----------------
__device__ fp16 g_x1[BATCH * HD];
__device__ fp16 g_u1[BATCH * HD], g_u2[BATCH * HD];
__device__ fp16 g_t1[BATCH * HD], g_t2[BATCH * HD];
__device__ float g_pre[BATCH * HD];                 // GEMM1 out, reused for GEMM3 out
__device__ float g_Pkv[(size_t)BATCH * 2 * HD];     // k | v
__device__ float g_Pzd[(size_t)BATCH * 2 * HD];     // z_pre | d_pre
__device__ float g_z[BATCH * HD];
__device__ fp16 g_W_in[HD * HD];
__device__ fp16 g_W_kv[2 * HD * HD];
__device__ fp16 g_W_zd[2 * HD * HD];
__device__ fp16 g_W_h[HD * HD];

// ---------------- helpers ----------------
__device__ __forceinline__ uint32_t smem_u32(const void* p) {
    return (uint32_t)__cvta_generic_to_shared(p);
}
__device__ __forceinline__ void cp16(uint32_t dst, const void* src) {
    asm volatile("cp.async.cg.shared.global [%0], [%1], 16;\n" :: "r"(dst), "l"(src));
}
__device__ __forceinline__ void ldm4(uint32_t (&r)[4], uint32_t addr) {
    asm volatile("ldmatrix.sync.aligned.m8n8.x4.shared.b16 {%0,%1,%2,%3}, [%4];\n"
                 : "=r"(r[0]), "=r"(r[1]), "=r"(r[2]), "=r"(r[3]) : "r"(addr));
}
__device__ __forceinline__ void mma16816(float (&d)[4], const uint32_t (&a)[4],
                                         uint32_t b0, uint32_t b1) {
    asm volatile("mma.sync.aligned.m16n8k16.row.col.f32.f16.f16.f32 "
                 "{%0,%1,%2,%3}, {%4,%5,%6,%7}, {%8,%9}, {%0,%1,%2,%3};\n"
                 : "+f"(d[0]), "+f"(d[1]), "+f"(d[2]), "+f"(d[3])
                 : "r"(a[0]), "r"(a[1]), "r"(a[2]), "r"(a[3]), "r"(b0), "r"(b1));
}
__device__ __forceinline__ float sigf(float x) { return 1.0f / (1.0f + __expf(-x)); }

__device__ __forceinline__ void split_store2(fp16* hi, fp16* lo, float a, float b) {
    fp16 ha = __float2half_rn(a);
    fp16 hb = __float2half_rn(b);
    *reinterpret_cast<__half2*>(hi) = __halves2half2(ha, hb);
    fp16 la = __float2half_rn(a - __half2float(ha));
    fp16 lb = __float2half_rn(b - __half2float(hb));
    *reinterpret_cast<__half2*>(lo) = __halves2half2(la, lb);
}

// ---------------- weight prep: transpose to [N][K] fp16 ----------------
__global__ void prep_weights(const float* __restrict__ W_in, const float* __restrict__ W_z,
                             const float* __restrict__ W_k, const float* __restrict__ W_v,
                             const float* __restrict__ W_d, const float* __restrict__ W_h) {
    int idx = blockIdx.x * 256 + threadIdx.x;
    if (idx >= 6 * HD * HD) return;
    int mat = idx / (HD * HD);
    int e = idx % (HD * HD);
    int k = e / HD, n = e % HD;
    const float* W;
    fp16* D;
    int dst;
    if (mat == 0) {
        W = W_in; D = g_W_in; dst = n * HD + k;
    } else if (mat == 1) {
        W = W_z; D = g_W_zd; dst = n * HD + k;                 // zd rows [0,512)
    } else if (mat == 2) {
        W = W_k; D = g_W_kv; dst = n * HD + k;                 // kv rows [0,512)
    } else if (mat == 3) {
        W = W_v; D = g_W_kv; dst = (HD + n) * HD + k;          // kv rows [512,1024)
    } else if (mat == 4) {
        W = W_d; D = g_W_zd; dst = (HD + n) * HD + k;          // zd rows [512,1024)
    } else {
        W = W_h; D = g_W_h; dst = n * HD + k;
    }
    D[dst] = __float2half_rn(W[e]);   // W[k][n], coalesced read over n
}

// ---------------- x -> single fp16 ----------------
__global__ void conv_x_kernel(const float* __restrict__ x) {
    int i = blockIdx.x * 256 + threadIdx.x;  // float4 index
    float4 v = reinterpret_cast<const float4*>(x)[i];
    __half2 a = __halves2half2(__float2half_rn(v.x), __float2half_rn(v.y));
    __half2 b = __halves2half2(__float2half_rn(v.z), __float2half_rn(v.w));
    *reinterpret_cast<__half2*>(g_x1 + (size_t)i * 4) = a;
    *reinterpret_cast<__half2*>(g_x1 + (size_t)i * 4 + 2) = b;
}

// ---------------- split-fp16 GEMM: C[M,N] = A[M,512] @ W[512,N] ----------------
// Round-6 proven structure: 2-stage double buffer, two syncs per stage,
// separate compute passes per A term.
// WHICH==0: x @ W_in   (1 term, N=512)  -> g_pre
// WHICH==1: u @ W_kv   (2 terms, N=1024)-> g_Pkv
// WHICH==2: t @ W_h    (2 terms, N=512) -> g_pre
// WHICH==3: u @ W_zd   (1 term, N=1024) -> g_Pzd
#define BM 128
#define BN 128
#define BK 32
#define KST 40                         // padded row stride (fp16) = 80 bytes
#define TILEB (BM * KST * 2)           // 10240 bytes per [128][40] fp16 tile
#define NSTG 16                        // 512 / 32

template <int WHICH>
__global__ void __launch_bounds__(256, 2) gemm2_kernel() {
    constexpr int NT = (WHICH == 0 || WHICH == 3) ? 1 : 2;   // A terms
    constexpr int TPS = NT + 1;                              // tiles per stage
    const fp16* A1 = (WHICH == 0) ? g_x1 : (WHICH == 2) ? g_t1 : g_u1;
    const fp16* A2 = (WHICH == 2) ? g_t2 : g_u2;             // used only when NT==2
    const fp16* Bp = (WHICH == 0) ? g_W_in : (WHICH == 1) ? g_W_kv
                   : (WHICH == 2) ? g_W_h : g_W_zd;
    float* C = (WHICH == 1) ? g_Pkv : (WHICH == 3) ? g_Pzd : g_pre;
    const int N = (WHICH == 1 || WHICH == 3) ? 2 * HD : HD;

    extern __shared__ __align__(16) char sm[];
    auto tile = [&](int stage, int sel) -> fp16* {   // sel: 0..NT-1 = A terms, NT = B
        return reinterpret_cast<fp16*>(sm + (size_t)(stage * TPS + sel) * TILEB);
    };

    const int tid = threadIdx.x;
    const int m0 = blockIdx.y * BM;
    const int n0 = blockIdx.x * BN;
    const int warp = tid >> 5, lane = tid & 31;
    const int wm = (warp >> 1) * 32;  // 4 warps along M
    const int wn = (warp & 1) * 64;   // 2 warps along N

    float acc[2][8][4];
#pragma unroll
    for (int i = 0; i < 2; i++)
#pragma unroll
        for (int j = 0; j < 8; j++)
#pragma unroll
            for (int q = 0; q < 4; q++) acc[i][j][q] = 0.f;

    auto load_stage = [&](int s) {
        const int st = s & 1;
        const int k0 = s * BK;
        fp16* a1 = tile(st, 0);
        fp16* bb = tile(st, NT);
#pragma unroll
        for (int i = 0; i < 2; i++) {
            int c = i * 256 + tid;          // 0..511
            int row = c >> 2;               // 0..127
            int col = (c & 3) * 8;          // fp16 col offset within 32
            uint32_t d = (uint32_t)(row * KST + col) * 2;  // byte offset
            size_t offA = (size_t)(m0 + row) * HD + k0 + col;
            cp16(smem_u32(a1) + d, A1 + offA);
            if (NT == 2) cp16(smem_u32(tile(st, 1)) + d, A2 + offA);
            size_t offB = (size_t)(n0 + row) * HD + k0 + col;
            cp16(smem_u32(bb) + d, Bp + offB);
        }
        asm volatile("cp.async.commit_group;\n");
    };

    auto compute_pass = [&](const fp16* At, const fp16* Bt) {
#pragma unroll
        for (int kk = 0; kk < BK; kk += 16) {
            uint32_t aF[2][4];
#pragma unroll
            for (int mi = 0; mi < 2; mi++) {
                uint32_t ad = smem_u32(At + (wm + mi * 16 + (lane & 15)) * KST
                                          + kk + ((lane >> 4) << 3));
                ldm4(aF[mi], ad);
            }
            uint32_t bF[4][4];
#pragma unroll
            for (int nb = 0; nb < 4; nb++) {
                uint32_t bd = smem_u32(Bt + (wn + nb * 16 + (lane & 7) + ((lane >> 4) << 3)) * KST
                                          + kk + (((lane >> 3) & 1) << 3));
                ldm4(bF[nb], bd);
            }
#pragma unroll
            for (int mi = 0; mi < 2; mi++)
#pragma unroll
                for (int ni = 0; ni < 8; ni++)
                    mma16816(acc[mi][ni], aF[mi], bF[ni >> 1][(ni & 1) * 2],
                             bF[ni >> 1][(ni & 1) * 2 + 1]);
        }
    };

    load_stage(0);
    load_stage(1);

    for (int s = 0; s < NSTG; ++s) {
        const int st = s & 1;
        if (s == NSTG - 1) asm volatile("cp.async.wait_group 0;\n");
        else               asm volatile("cp.async.wait_group 1;\n");
        __syncthreads();
        compute_pass(tile(st, 0), tile(st, NT));               // A1 * B
        if (NT == 2) compute_pass(tile(st, 1), tile(st, NT));  // A2 * B
        __syncthreads();
        if (s + 2 < NSTG) load_stage(s + 2);
    }

    // epilogue: write fp32 C
#pragma unroll
    for (int mi = 0; mi < 2; mi++)
#pragma unroll
        for (int ni = 0; ni < 8; ni++) {
            int r = m0 + wm + mi * 16 + (lane >> 2);
            int c = n0 + wn + ni * 8 + (lane & 3) * 2;
            *reinterpret_cast<float2*>(&C[(size_t)r * N + c]) =
                make_float2(acc[mi][ni][0], acc[mi][ni][1]);
            *reinterpret_cast<float2*>(&C[(size_t)(r + 8) * N + c]) =
                make_float2(acc[mi][ni][2], acc[mi][ni][3]);
        }
}

#define SMEM_G1 (4 * TILEB)   // 40960: 2 stages * (A1, B)
#define SMEM_G2 (6 * TILEB)   // 61440: 2 stages * (A1, A2, B)

// ---------------- LN over g_pre -> u (fp16 hi/lo) ----------------
__global__ void ln_u_kernel(const float* __restrict__ bias, const float* __restrict__ gamma,
                            const float* __restrict__ beta) {
    int row = blockIdx.x * 8 + (threadIdx.x >> 5);
    int lane = threadIdx.x & 31;
    const float* p = g_pre + (size_t)row * HD;
    float v[16];
    float sm = 0.f, sq = 0.f;
#pragma unroll
    for (int i = 0; i < 4; i++) {
        int c = i * 128 + lane * 4;
        float4 x4 = *reinterpret_cast<const float4*>(p + c);
        float4 b4 = *reinterpret_cast<const float4*>(bias + c);
        float t0 = x4.x + b4.x, t1 = x4.y + b4.y, t2 = x4.z + b4.z, t3 = x4.w + b4.w;
        v[i * 4 + 0] = t0; v[i * 4 + 1] = t1; v[i * 4 + 2] = t2; v[i * 4 + 3] = t3;
        sm += t0 + t1 + t2 + t3;
        sq += t0 * t0 + t1 * t1 + t2 * t2 + t3 * t3;
    }
#pragma unroll
    for (int o = 16; o; o >>= 1) {
        sm += __shfl_xor_sync(0xffffffffu, sm, o);
        sq += __shfl_xor_sync(0xffffffffu, sq, o);
    }
    float mean = sm * (1.f / HD);
    float inv = rsqrtf(fmaxf(sq * (1.f / HD) - mean * mean, 0.f) + 1e-5f);
#pragma unroll
    for (int i = 0; i < 4; i++) {
        int c = i * 128 + lane * 4;
        float4 g4 = *reinterpret_cast<const float4*>(gamma + c);
        float4 b4 = *reinterpret_cast<const float4*>(beta + c);
        float u0 = (v[i * 4 + 0] - mean) * inv * g4.x + b4.x;
        float u1 = (v[i * 4 + 1] - mean) * inv * g4.y + b4.y;
        float u2 = (v[i * 4 + 2] - mean) * inv * g4.z + b4.z;
        float u3 = (v[i * 4 + 3] - mean) * inv * g4.w + b4.w;
        size_t idx = (size_t)row * HD + c;
        split_store2(g_u1 + idx, g_u2 + idx, u0, u1);
        split_store2(g_u1 + idx + 2, g_u2 + idx + 2, u2, u3);
    }
}

// ---------------- epilogue 1: z, s, t ----------------
__global__ void epi1_kernel(const float* __restrict__ s_prev, const float* __restrict__ bz,
                            const float* __restrict__ glz, const float* __restrict__ blz,
                            const float* __restrict__ bk, const float* __restrict__ bv,
                            const float* __restrict__ bd, float* __restrict__ out_s) {
    int row = blockIdx.x * 8 + (threadIdx.x >> 5);
    int lane = threadIdx.x & 31;
    const float* Pkv = g_Pkv + (size_t)row * (2 * HD);
    const float* Pzd = g_Pzd + (size_t)row * (2 * HD);
    float zp[16];
    float sm = 0.f, sq = 0.f;
#pragma unroll
    for (int i = 0; i < 4; i++) {
        int c = i * 128 + lane * 4;
        float4 z4 = *reinterpret_cast<const float4*>(Pzd + c);
        float4 b4 = *reinterpret_cast<const float4*>(bz + c);
        float t0 = z4.x + b4.x, t1 = z4.y + b4.y, t2 = z4.z + b4.z, t3 = z4.w + b4.w;
        zp[i * 4 + 0] = t0; zp[i * 4 + 1] = t1; zp[i * 4 + 2] = t2; zp[i * 4 + 3] = t3;
        sm += t0 + t1 + t2 + t3;
        sq += t0 * t0 + t1 * t1 + t2 * t2 + t3 * t3;
    }
#pragma unroll
    for (int o = 16; o; o >>= 1) {
        sm += __shfl_xor_sync(0xffffffffu, sm, o);
        sq += __shfl_xor_sync(0xffffffffu, sq, o);
    }
    float mean = sm * (1.f / HD);
    float inv = rsqrtf(fmaxf(sq * (1.f / HD) - mean * mean, 0.f) + 1e-5f);
#pragma unroll
    for (int i = 0; i < 4; i++) {
        int c = i * 128 + lane * 4;
        size_t idx = (size_t)row * HD + c;
        float4 g4 = *reinterpret_cast<const float4*>(glz + c);
        float4 bb4 = *reinterpret_cast<const float4*>(blz + c);
        float z0 = sigf((zp[i * 4 + 0] - mean) * inv * g4.x + bb4.x);
        float z1 = sigf((zp[i * 4 + 1] - mean) * inv * g4.y + bb4.y);
        float z2 = sigf((zp[i * 4 + 2] - mean) * inv * g4.z + bb4.z);
        float z3 = sigf((zp[i * 4 + 3] - mean) * inv * g4.w + bb4.w);

        float4 k4 = *reinterpret_cast<const float4*>(Pkv + c);
        float4 bk4 = *reinterpret_cast<const float4*>(bk + c);
        float4 v4 = *reinterpret_cast<const float4*>(Pkv + HD + c);
        float4 bv4 = *reinterpret_cast<const float4*>(bv + c);
        float4 d4 = *reinterpret_cast<const float4*>(Pzd + HD + c);
        float4 bd4 = *reinterpret_cast<const float4*>(bd + c);
        float4 sp = *reinterpret_cast<const float4*>(s_prev + idx);

        float kk0 = k4.x + bk4.x, kk1 = k4.y + bk4.y, kk2 = k4.z + bk4.z, kk3 = k4.w + bk4.w;
        float vv0 = v4.x + bv4.x, vv1 = v4.y + bv4.y, vv2 = v4.z + bv4.z, vv3 = v4.w + bv4.w;
        float dc0 = sigf(d4.x + bd4.x), dc1 = sigf(d4.y + bd4.y);
        float dc2 = sigf(d4.z + bd4.z), dc3 = sigf(d4.w + bd4.w);
        float s0 = dc0 * sp.x + kk0 * vv0;
        float s1 = dc1 * sp.y + kk1 * vv1;
        float s2 = dc2 * sp.z + kk2 * vv2;
        float s3 = dc3 * sp.w + kk3 * vv3;
        *reinterpret_cast<float4*>(out_s + idx) = make_float4(s0, s1, s2, s3);

        __half2 uh0 = *reinterpret_cast<const __half2*>(g_u1 + idx);
        __half2 ul0 = *reinterpret_cast<const __half2*>(g_u2 + idx);
        __half2 uh1 = *reinterpret_cast<const __half2*>(g_u1 + idx + 2);
        __half2 ul1 = *reinterpret_cast<const __half2*>(g_u2 + idx + 2);
        float u0 = __half2float(uh0.x) + __half2float(ul0.x);
        float u1 = __half2float(uh0.y) + __half2float(ul0.y);
        float u2 = __half2float(uh1.x) + __half2float(ul1.x);
        float u3 = __half2float(uh1.y) + __half2float(ul1.y);
        split_store2(g_t1 + idx, g_t2 + idx, u0 + s0, u1 + s1);
        split_store2(g_t1 + idx + 2, g_t2 + idx + 2, u2 + s2, u3 + s3);
        *reinterpret_cast<float4*>(&g_z[idx]) = make_float4(z0, z1, z2, z3);
    }
}

// ---------------- epilogue 2: h ----------------
__global__ void epi2_kernel(const float* __restrict__ h_prev, const float* __restrict__ bh,
                            const float* __restrict__ glh, const float* __restrict__ blh,
                            float* __restrict__ out_h) {
    int row = blockIdx.x * 8 + (threadIdx.x >> 5);
    int lane = threadIdx.x & 31;
    const float* p = g_pre + (size_t)row * HD;
    float v[16];
    float sm = 0.f, sq = 0.f;
#pragma unroll
    for (int i = 0; i < 4; i++) {
        int c = i * 128 + lane * 4;
        float4 x4 = *reinterpret_cast<const float4*>(p + c);
        float4 b4 = *reinterpret_cast<const float4*>(bh + c);
        float t0 = x4.x + b4.x, t1 = x4.y + b4.y, t2 = x4.z + b4.z, t3 = x4.w + b4.w;
        v[i * 4 + 0] = t0; v[i * 4 + 1] = t1; v[i * 4 + 2] = t2; v[i * 4 + 3] = t3;
        sm += t0 + t1 + t2 + t3;
        sq += t0 * t0 + t1 * t1 + t2 * t2 + t3 * t3;
    }
#pragma unroll
    for (int o = 16; o; o >>= 1) {
        sm += __shfl_xor_sync(0xffffffffu, sm, o);
        sq += __shfl_xor_sync(0xffffffffu, sq, o);
    }
    float mean = sm * (1.f / HD);
    float inv = rsqrtf(fmaxf(sq * (1.f / HD) - mean * mean, 0.f) + 1e-5f);
#pragma unroll
    for (int i = 0; i < 4; i++) {
        int c = i * 128 + lane * 4;
        size_t idx = (size_t)row * HD + c;
        float4 g4 = *reinterpret_cast<const float4*>(glh + c);
        float4 b4 = *reinterpret_cast<const float4*>(blh + c);
        float c0 = tanhf((v[i * 4 + 0] - mean) * inv * g4.x + b4.x);
        float c1 = tanhf((v[i * 4 + 1] - mean) * inv * g4.y + b4.y);
        float c2 = tanhf((v[i * 4 + 2] - mean) * inv * g4.z + b4.z);
        float c3 = tanhf((v[i * 4 + 3] - mean) * inv * g4.w + b4.w);
        float4 z4 = *reinterpret_cast<const float4*>(&g_z[idx]);
        float4 hp = *reinterpret_cast<const float4*>(h_prev + idx);
        float h0 = (1.f - z4.x) * c0 + z4.x * hp.x;
        float h1 = (1.f - z4.y) * c1 + z4.y * hp.y;
        float h2 = (1.f - z4.z) * c2 + z4.z * hp.z;
        float h3 = (1.f - z4.w) * c3 + z4.w * hp.w;
        *reinterpret_cast<float4*>(out_h + idx) = make_float4(h0, h1, h2, h3);
    }
}

// ---------------- launch ----------------
extern "C" void kernel_launch(void* const* d_in, const int* in_sizes, int n_in,
                              void* d_out, int out_size) {
    const float* x       = (const float*)d_in[0];
    const float* h_prev  = (const float*)d_in[1];
    const float* s_prev  = (const float*)d_in[2];
    const float* W_in    = (const float*)d_in[3];
    const float* b_in    = (const float*)d_in[4];
    const float* g_ln_in = (const float*)d_in[5];
    const float* b_ln_in = (const float*)d_in[6];
    const float* g_ln_z  = (const float*)d_in[9];
    const float* b_ln_z  = (const float*)d_in[10];
    const float* g_ln_h  = (const float*)d_in[11];
    const float* b_ln_h  = (const float*)d_in[12];
    const float* W_z     = (const float*)d_in[15];
    const float* b_z     = (const float*)d_in[16];
    const float* W_k     = (const float*)d_in[17];
    const float* b_k     = (const float*)d_in[18];
    const float* W_v     = (const float*)d_in[19];
    const float* b_v     = (const float*)d_in[20];
    const float* W_h     = (const float*)d_in[21];
    const float* b_h     = (const float*)d_in[22];
    const float* W_d     = (const float*)d_in[23];
    const float* b_d     = (const float*)d_in[24];

    float* out_h = (float*)d_out;
    float* out_s = out_h + (size_t)BATCH * HD;

    cudaFuncSetAttribute(gemm2_kernel<0>, cudaFuncAttributeMaxDynamicSharedMemorySize, SMEM_G1);
    cudaFuncSetAttribute(gemm2_kernel<1>, cudaFuncAttributeMaxDynamicSharedMemorySize, SMEM_G2);
    cudaFuncSetAttribute(gemm2_kernel<2>, cudaFuncAttributeMaxDynamicSharedMemorySize, SMEM_G2);
    cudaFuncSetAttribute(gemm2_kernel<3>, cudaFuncAttributeMaxDynamicSharedMemorySize, SMEM_G1);

    prep_weights<<<(6 * HD * HD + 255) / 256, 256>>>(W_in, W_z, W_k, W_v, W_d, W_h);
    conv_x_kernel<<<BATCH * HD / 4 / 256, 256>>>(x);

    gemm2_kernel<0><<<dim3(HD / BN, BATCH / BM), 256, SMEM_G1>>>();
    ln_u_kernel<<<BATCH / 8, 256>>>(b_in, g_ln_in, b_ln_in);

    gemm2_kernel<1><<<dim3(2 * HD / BN, BATCH / BM), 256, SMEM_G2>>>();
    gemm2_kernel<3><<<dim3(2 * HD / BN, BATCH / BM), 256, SMEM_G1>>>();
    epi1_kernel<<<BATCH / 8, 256>>>(s_prev, b_z, g_ln_z, b_ln_z, b_k, b_v, b_d, out_s);

    gemm2_kernel<2><<<dim3(HD / BN, BATCH / BM), 256, SMEM_G2>>>();
    epi2_kernel<<<BATCH / 8, 256>>>(h_prev, b_h, g_ln_h, b_ln_h, out_h);
}